// round 7
// baseline (speedup 1.0000x reference)
#include <cuda_runtime.h>
#include <cuda_bf16.h>
#include <cstdint>
#include <math.h>

// Problem: B=64, S=1024, I=256, H=256, G=3H=768, two GRU layers.
#define PB 64
#define PS 1024
#define PH 256
#define PG 768
#define BSH (PB * PS * PH)   // 16,777,216

// Scratch (device globals: the sanctioned no-alloc workaround)
__device__ float g_xg[(size_t)PB * PS * PG];  // per-layer input projections [B,S,768]
__device__ float g_h1[(size_t)PB * PS * PH];  // layer-0 hidden states [B,S,256]

// ---------------------------------------------------------------------------
// GEMM: out[m][n] = sum_k A[m][k] * W[n][k] + bias[n]
// A: [65536][256], W: [768][256], out: [65536][768]
// BM=128, BN=64, BK=32, 256 threads, 8x4 per thread.
// ---------------------------------------------------------------------------
__global__ __launch_bounds__(256) void gemm_xg(
    const float* __restrict__ A, const float* __restrict__ W,
    const float* __restrict__ bias, float* __restrict__ out)
{
    __shared__ float Xs[32][132];  // [k][m] transposed, padded
    __shared__ float Ws[32][68];   // [k][n] transposed, padded

    const int t  = threadIdx.x;
    const int bn = blockIdx.x;   // 0..11
    const int bm = blockIdx.y;   // 0..511
    const int tx = t & 15;       // n-group (4 cols)
    const int ty = t >> 4;       // m-group (8 rows)

    const float* Ablk = A + (size_t)bm * 128 * 256;
    const float* Wblk = W + (size_t)bn * 64 * 256;

    float acc[8][4];
#pragma unroll
    for (int i = 0; i < 8; i++)
#pragma unroll
        for (int j = 0; j < 4; j++) acc[i][j] = 0.f;

    const int a_row = t >> 3;  // 0..31
    const int a_kc  = t & 7;   // 0..7 (float4 along K)

    for (int kt = 0; kt < 256; kt += 32) {
#pragma unroll
        for (int r = 0; r < 4; r++) {
            int row = a_row + r * 32;
            float4 v = *reinterpret_cast<const float4*>(Ablk + (size_t)row * 256 + kt + a_kc * 4);
            Xs[a_kc * 4 + 0][row] = v.x;
            Xs[a_kc * 4 + 1][row] = v.y;
            Xs[a_kc * 4 + 2][row] = v.z;
            Xs[a_kc * 4 + 3][row] = v.w;
        }
#pragma unroll
        for (int r = 0; r < 2; r++) {
            int row = a_row + r * 32;
            float4 v = *reinterpret_cast<const float4*>(Wblk + (size_t)row * 256 + kt + a_kc * 4);
            Ws[a_kc * 4 + 0][row] = v.x;
            Ws[a_kc * 4 + 1][row] = v.y;
            Ws[a_kc * 4 + 2][row] = v.z;
            Ws[a_kc * 4 + 3][row] = v.w;
        }
        __syncthreads();

#pragma unroll
        for (int kk = 0; kk < 32; kk++) {
            float4 a0 = *reinterpret_cast<const float4*>(&Xs[kk][ty * 8]);
            float4 a1 = *reinterpret_cast<const float4*>(&Xs[kk][ty * 8 + 4]);
            float4 b4 = *reinterpret_cast<const float4*>(&Ws[kk][tx * 4]);
            float a[8] = {a0.x, a0.y, a0.z, a0.w, a1.x, a1.y, a1.z, a1.w};
            float b[4] = {b4.x, b4.y, b4.z, b4.w};
#pragma unroll
            for (int i = 0; i < 8; i++)
#pragma unroll
                for (int j = 0; j < 4; j++) acc[i][j] += a[i] * b[j];
        }
        __syncthreads();
    }

    float4 bv = *reinterpret_cast<const float4*>(bias + bn * 64 + tx * 4);
#pragma unroll
    for (int i = 0; i < 8; i++) {
        size_t m = (size_t)bm * 128 + ty * 8 + i;
        float4 o;
        o.x = acc[i][0] + bv.x;
        o.y = acc[i][1] + bv.y;
        o.z = acc[i][2] + bv.z;
        o.w = acc[i][3] + bv.w;
        *reinterpret_cast<float4*>(out + m * 768 + bn * 64 + tx * 4) = o;
    }
}

// ---------------------------------------------------------------------------
// GRU recurrence: cluster of 4 CTAs handles 2 batches. CTA rank r owns hidden
// indices [64r, 64r+64) => W_hh rows {j, 256+j, 512+j}. W slice lives in SMEM
// (fp32, k-major, permuted) for all 1024 steps. h double-buffered in SMEM,
// broadcast to the 4 cluster CTAs via DSMEM + barrier.cluster per step.
// ---------------------------------------------------------------------------
#define KP 196                        // padded k-stride (floats) of sW
#define SW_FLOATS (256 * KP)          // 50176
#define SH_OFF SW_FLOATS              // h: [2][2][256] = 1024 floats
#define P_OFF  (SH_OFF + 1024)        // partials: [8][2][192] = 3072 floats
#define REC_SMEM_BYTES ((P_OFF + 3072) * 4)  // 217,088 B

__device__ __forceinline__ uint32_t smem_u32(const void* p) {
    uint32_t a;
    asm("{ .reg .u64 t; cvta.to.shared.u64 t, %1; cvt.u32.u64 %0, t; }"
        : "=r"(a) : "l"(p));
    return a;
}

__global__ void __launch_bounds__(256, 1) __cluster_dims__(4, 1, 1)
gru_rec(const float* __restrict__ xg, const float* __restrict__ Whh,
        const float* __restrict__ bhh,
        float* __restrict__ dA, long long sA, int oA,
        float* __restrict__ dB, long long sB, int oB)
{
    extern __shared__ float sm[];
    float* sW = sm;             // [256][KP]
    float* sh = sm + SH_OFF;    // [2][2][256]
    float* p  = sm + P_OFF;     // [8][2][192]

    const int t    = threadIdx.x;
    const int rank = blockIdx.x & 3;
    const int pair = blockIdx.x >> 2;   // 0..31
    const int wid  = t >> 5;
    const int lane = t & 31;

    // --- Load W_hh slice into SMEM, transposed + permuted for the matvec ---
    for (int rl = wid; rl < 192; rl += 8) {
        int g  = rl >> 6;
        int jj = rl & 63;
        int rowg = g * 256 + rank * 64 + jj;
        int jq = rl / 12, m = rl - jq * 12, ii = m >> 2, e = m & 3;
        int pos = (ii * 16 + jq) * 4 + e;
        const float* src = Whh + (size_t)rowg * 256;
        for (int k = lane; k < 256; k += 32)
            sW[k * KP + pos] = src[k];
    }
    for (int i = t; i < 1024; i += 256) sh[i] = 0.f;  // h0 = 0 (both buffers)
    __syncthreads();

    // matvec role
    const int kh = t >> 5;        // k-chunk 0..7
    const int b  = lane & 1;      // batch within pair
    const int jq = lane >> 1;     // row group 0..15 (12 rows each)

    // reduction role (t < 128)
    const int rb = t >> 6;
    const int rj = t & 63;
    const int jg = rank * 64 + rj;
    const long long bG_r = (long long)pair * 2 + rb;
    float bh0 = 0.f, bh1 = 0.f, bh2 = 0.f;
    if (t < 128) {
        bh0 = bhh[jg];
        bh1 = bhh[256 + jg];
        bh2 = bhh[512 + jg];
    }

    const uint32_t shbase = smem_u32(sh);

    for (int s = 0; s < PS; s++) {
        const int cur = s & 1, nxt = cur ^ 1;

        // prefetch xg (consumed after syncthreads; ~1500 cyc to hide latency)
        float xr = 0.f, xz = 0.f, xn = 0.f;
        if (t < 128) {
            const float* xp = xg + ((bG_r << 10) + s) * 768;
            xr = xp[jg];
            xz = xp[256 + jg];
            xn = xp[512 + jg];
        }

        // --- matvec: partial hg for 12 rows x 32 k ---
        float acc[12];
#pragma unroll
        for (int i = 0; i < 12; i++) acc[i] = 0.f;
        const float4* h4 = reinterpret_cast<const float4*>(sh + cur * 512 + b * 256 + kh * 32);
#pragma unroll
        for (int k4 = 0; k4 < 8; k4++) {
            float4 hv = h4[k4];
            float hs[4] = {hv.x, hv.y, hv.z, hv.w};
#pragma unroll
            for (int kk = 0; kk < 4; kk++) {
                int k = kh * 32 + k4 * 4 + kk;
                const float4* wrow = reinterpret_cast<const float4*>(sW + k * KP + jq * 4);
                float4 w0 = wrow[0];
                float4 w1 = wrow[16];
                float4 w2 = wrow[32];
                float hx = hs[kk];
                acc[0] += w0.x * hx; acc[1]  += w0.y * hx; acc[2]  += w0.z * hx; acc[3]  += w0.w * hx;
                acc[4] += w1.x * hx; acc[5]  += w1.y * hx; acc[6]  += w1.z * hx; acc[7]  += w1.w * hx;
                acc[8] += w2.x * hx; acc[9]  += w2.y * hx; acc[10] += w2.z * hx; acc[11] += w2.w * hx;
            }
        }
        {
            float4* pp = reinterpret_cast<float4*>(p + kh * 384 + b * 192 + jq * 12);
            pp[0] = make_float4(acc[0], acc[1], acc[2], acc[3]);
            pp[1] = make_float4(acc[4], acc[5], acc[6], acc[7]);
            pp[2] = make_float4(acc[8], acc[9], acc[10], acc[11]);
        }
        __syncthreads();

        // --- reduce + gates + broadcast h_new ---
        if (t < 128) {
            float h0 = bh0, h1 = bh1, h2 = bh2;
#pragma unroll
            for (int q = 0; q < 8; q++) {
                const float* pq = p + q * 384 + rb * 192;
                h0 += pq[rj];
                h1 += pq[64 + rj];
                h2 += pq[128 + rj];
            }
            float hp = sh[cur * 512 + rb * 256 + jg];
            float r = 1.f / (1.f + expf(-(xr + h0)));
            float z = 1.f / (1.f + expf(-(xz + h1)));
            float n = tanhf(xn + r * h2);
            float hn = (1.f - z) * n + z * hp;

            uint32_t la = shbase + (uint32_t)((nxt * 512 + rb * 256 + jg) * 4);
#pragma unroll
            for (int rr = 0; rr < 4; rr++) {
                asm volatile(
                    "{\n\t.reg .b32 ra;\n\t"
                    "mapa.shared::cluster.u32 ra, %0, %1;\n\t"
                    "st.shared::cluster.f32 [ra], %2;\n\t}"
                    :: "r"(la), "r"(rr), "f"(hn) : "memory");
            }
            long long row = (bG_r << 10) + s;
            dA[row * sA + oA + jg] = hn;
            dB[row * sB + oB + jg] = hn;
        }
        asm volatile("barrier.cluster.arrive.aligned;" ::: "memory");
        asm volatile("barrier.cluster.wait.aligned;" ::: "memory");
    }
}

// ---------------------------------------------------------------------------
extern "C" void kernel_launch(void* const* d_in, const int* in_sizes, int n_in,
                              void* d_out, int out_size) {
    const float* inp   = (const float*)d_in[0];
    const float* W_ih0 = (const float*)d_in[1];
    const float* W_hh0 = (const float*)d_in[2];
    const float* b_ih0 = (const float*)d_in[3];
    const float* b_hh0 = (const float*)d_in[4];
    const float* W_ih1 = (const float*)d_in[5];
    const float* W_hh1 = (const float*)d_in[6];
    const float* b_ih1 = (const float*)d_in[7];
    const float* b_hh1 = (const float*)d_in[8];
    float* out = (float*)d_out;

    float *xgp = nullptr, *h1p = nullptr;
    cudaGetSymbolAddress((void**)&xgp, g_xg);
    cudaGetSymbolAddress((void**)&h1p, g_h1);

    cudaFuncSetAttribute(gru_rec, cudaFuncAttributeMaxDynamicSharedMemorySize,
                         REC_SMEM_BYTES);

    dim3 ggrid(12, 512);

    // Layer 0
    gemm_xg<<<ggrid, 256>>>(inp, W_ih0, b_ih0, xgp);
    gru_rec<<<128, 256, REC_SMEM_BYTES>>>(xgp, W_hh0, b_hh0,
                                          h1p, 256, 0,
                                          out + BSH, 512, 0);
    // Layer 1
    gemm_xg<<<ggrid, 256>>>(h1p, W_ih1, b_ih1, xgp);
    gru_rec<<<128, 256, REC_SMEM_BYTES>>>(xgp, W_hh1, b_hh1,
                                          out, 256, 0,
                                          out + BSH, 512, 256);
}

// round 9
// speedup vs baseline: 1.2183x; 1.2183x over previous
#include <cuda_runtime.h>
#include <cuda_bf16.h>
#include <cstdint>
#include <math.h>

// Problem: B=64, S=1024, I=256, H=256, G=3H=768, two GRU layers.
#define PB 64
#define PS 1024
#define PH 256
#define PG 768
#define BSH (PB * PS * PH)   // 16,777,216

// Scratch (device globals: the sanctioned no-alloc workaround)
__device__ float g_xg[(size_t)PB * PS * PG];  // per-layer input projections [B,S,768]
__device__ float g_h1[(size_t)PB * PS * PH];  // layer-0 hidden states [B,S,256]

// ---- f32x2 packed helpers (PTX-only path; ptxas won't emit FFMA2 from C++) ----
__device__ __forceinline__ void fma2(unsigned long long& d, unsigned long long a,
                                     unsigned long long b) {
    asm("fma.rn.f32x2 %0, %1, %2, %0;" : "+l"(d) : "l"(a), "l"(b));
}
__device__ __forceinline__ unsigned long long dup2(float x) {
    unsigned long long r;
    asm("mov.b64 %0, {%1, %1};" : "=l"(r) : "f"(x));
    return r;
}
__device__ __forceinline__ unsigned long long pack2(float lo, float hi) {
    unsigned long long r;
    asm("mov.b64 %0, {%1, %2};" : "=l"(r) : "f"(lo), "f"(hi));
    return r;
}
__device__ __forceinline__ float2 unpack2(unsigned long long v) {
    float lo, hi;
    asm("mov.b64 {%0, %1}, %2;" : "=f"(lo), "=f"(hi) : "l"(v));
    return make_float2(lo, hi);
}
__device__ __forceinline__ uint32_t smem_u32(const void* p) {
    uint32_t a;
    asm("{ .reg .u64 t; cvta.to.shared.u64 t, %1; cvt.u32.u64 %0, t; }"
        : "=r"(a) : "l"(p));
    return a;
}

// ---------------------------------------------------------------------------
// GEMM: out[m][n] = sum_k A[m][k] * W[n][k] + bias[n]
// A: [65536][256], W: [768][256], out: [65536][768]
// BM=128, BN=64, BK=32, 256 threads, 8x4 per thread, row-pair f32x2 accum.
// ---------------------------------------------------------------------------
__global__ __launch_bounds__(256) void gemm_xg(
    const float* __restrict__ A, const float* __restrict__ W,
    const float* __restrict__ bias, float* __restrict__ out)
{
    __shared__ __align__(16) float Xs[32][132];  // [k][m] transposed, padded
    __shared__ __align__(16) float Ws[32][68];   // [k][n] transposed, padded

    const int t  = threadIdx.x;
    const int bn = blockIdx.x;   // 0..11
    const int bm = blockIdx.y;   // 0..511
    const int tx = t & 15;       // n-group (4 cols)
    const int ty = t >> 4;       // m-group (8 rows = 4 row-pairs)

    const float* Ablk = A + (size_t)bm * 128 * 256;
    const float* Wblk = W + (size_t)bn * 64 * 256;

    unsigned long long acc[4][4];  // [row-pair][col], f32x2 packed (row2p, row2p+1)
#pragma unroll
    for (int i = 0; i < 4; i++)
#pragma unroll
        for (int j = 0; j < 4; j++) acc[i][j] = 0ull;

    const int a_row = t >> 3;  // 0..31
    const int a_kc  = t & 7;   // 0..7 (float4 along K)

    for (int kt = 0; kt < 256; kt += 32) {
#pragma unroll
        for (int r = 0; r < 4; r++) {
            int row = a_row + r * 32;
            float4 v = *reinterpret_cast<const float4*>(Ablk + (size_t)row * 256 + kt + a_kc * 4);
            Xs[a_kc * 4 + 0][row] = v.x;
            Xs[a_kc * 4 + 1][row] = v.y;
            Xs[a_kc * 4 + 2][row] = v.z;
            Xs[a_kc * 4 + 3][row] = v.w;
        }
#pragma unroll
        for (int r = 0; r < 2; r++) {
            int row = a_row + r * 32;
            float4 v = *reinterpret_cast<const float4*>(Wblk + (size_t)row * 256 + kt + a_kc * 4);
            Ws[a_kc * 4 + 0][row] = v.x;
            Ws[a_kc * 4 + 1][row] = v.y;
            Ws[a_kc * 4 + 2][row] = v.z;
            Ws[a_kc * 4 + 3][row] = v.w;
        }
        __syncthreads();

#pragma unroll
        for (int kk = 0; kk < 32; kk++) {
            // A row-pairs load directly as b64 (no packing movs)
            unsigned long long a01 = *reinterpret_cast<const unsigned long long*>(&Xs[kk][ty * 8 + 0]);
            unsigned long long a23 = *reinterpret_cast<const unsigned long long*>(&Xs[kk][ty * 8 + 2]);
            unsigned long long a45 = *reinterpret_cast<const unsigned long long*>(&Xs[kk][ty * 8 + 4]);
            unsigned long long a67 = *reinterpret_cast<const unsigned long long*>(&Xs[kk][ty * 8 + 6]);
            float4 b4 = *reinterpret_cast<const float4*>(&Ws[kk][tx * 4]);
            unsigned long long b0 = dup2(b4.x), b1 = dup2(b4.y), b2 = dup2(b4.z), b3 = dup2(b4.w);
            fma2(acc[0][0], a01, b0); fma2(acc[0][1], a01, b1); fma2(acc[0][2], a01, b2); fma2(acc[0][3], a01, b3);
            fma2(acc[1][0], a23, b0); fma2(acc[1][1], a23, b1); fma2(acc[1][2], a23, b2); fma2(acc[1][3], a23, b3);
            fma2(acc[2][0], a45, b0); fma2(acc[2][1], a45, b1); fma2(acc[2][2], a45, b2); fma2(acc[2][3], a45, b3);
            fma2(acc[3][0], a67, b0); fma2(acc[3][1], a67, b1); fma2(acc[3][2], a67, b2); fma2(acc[3][3], a67, b3);
        }
        __syncthreads();
    }

    float4 bv = *reinterpret_cast<const float4*>(bias + bn * 64 + tx * 4);
#pragma unroll
    for (int i = 0; i < 4; i++) {
        float2 c0 = unpack2(acc[i][0]);
        float2 c1 = unpack2(acc[i][1]);
        float2 c2 = unpack2(acc[i][2]);
        float2 c3 = unpack2(acc[i][3]);
        size_t m0 = (size_t)bm * 128 + ty * 8 + 2 * i;
        float4 o0, o1;
        o0.x = c0.x + bv.x; o0.y = c1.x + bv.y; o0.z = c2.x + bv.z; o0.w = c3.x + bv.w;
        o1.x = c0.y + bv.x; o1.y = c1.y + bv.y; o1.z = c2.y + bv.z; o1.w = c3.y + bv.w;
        *reinterpret_cast<float4*>(out + m0 * 768 + bn * 64 + tx * 4) = o0;
        *reinterpret_cast<float4*>(out + (m0 + 1) * 768 + bn * 64 + tx * 4) = o1;
    }
}

// ---------------------------------------------------------------------------
// GRU recurrence: cluster of 4 CTAs handles 2 batches. CTA rank r owns hidden
// indices [64r, 64r+64) => W_hh rows {g*256 + 64r + j}. The 192x256 W slice
// lives in REGISTERS (row-pair f32x2 packed: 96 b64/thread). h is read from
// SMEM as warp-uniform broadcasts, double-buffered, and exchanged between the
// 4 cluster CTAs via DSMEM stores + barrier.cluster per step.
// Thread (kh = t>>5, lane = t&31): rows 6*lane..6*lane+5, k in [32*kh, 32*kh+32).
// ---------------------------------------------------------------------------
__global__ void __launch_bounds__(256, 1) __cluster_dims__(4, 1, 1)
gru_rec(const float* __restrict__ xg, const float* __restrict__ Whh,
        const float* __restrict__ bhh,
        float* __restrict__ dA, long long sA, int oA,
        float* __restrict__ dB, long long sB, int oB)
{
    __shared__ __align__(16) float sh[1024];   // [2 dbuf][2 batch][256]
    __shared__ __align__(16) float pr[3072];   // [8 kh][2 batch][192 rows]

    const int t    = threadIdx.x;
    const int rank = blockIdx.x & 3;
    const int pair = blockIdx.x >> 2;   // 0..31
    const int kh   = t >> 5;            // k-chunk 0..7
    const int lane = t & 31;            // row-group (6 rows each)

    // --- Load W_hh slice into registers, row-pair packed ---
    unsigned long long w[3][32];
#pragma unroll
    for (int pch = 0; pch < 3; pch++) {
        int ra = 6 * lane + 2 * pch;
        int rb_ = ra + 1;
        const float* s0 = Whh + (size_t)(((ra  >> 6) << 8) + (rank << 6) + (ra  & 63)) * 256 + kh * 32;
        const float* s1 = Whh + (size_t)(((rb_ >> 6) << 8) + (rank << 6) + (rb_ & 63)) * 256 + kh * 32;
#pragma unroll
        for (int kk = 0; kk < 32; kk++)
            w[pch][kk] = pack2(s0[kk], s1[kk]);
    }

    for (int i = t; i < 1024; i += 256) sh[i] = 0.f;  // h0 = 0 (both buffers)
    __syncthreads();

    // epilogue role (t < 128)
    const int rb = t >> 6;
    const int rj = t & 63;
    const int jg = (rank << 6) + rj;
    const long long bG_r = (long long)pair * 2 + rb;
    float bh0 = 0.f, bh1 = 0.f, bh2 = 0.f;
    const float* xp_base = xg;
    if (t < 128) {
        bh0 = bhh[jg];
        bh1 = bhh[256 + jg];
        bh2 = bhh[512 + jg];
        xp_base = xg + (bG_r << 10) * 768;
    }

    const uint32_t shbase = smem_u32(sh);
    float2* const pp = reinterpret_cast<float2*>(pr + kh * 384 + 6 * lane);

    for (int s = 0; s < PS; s++) {
        const int cur = s & 1, nxt = cur ^ 1;

        // prefetch xg (consumed after syncthreads)
        float xr = 0.f, xz = 0.f, xn = 0.f;
        if (t < 128) {
            const float* xp = xp_base + (size_t)s * 768;
            xr = xp[jg];
            xz = xp[256 + jg];
            xn = xp[512 + jg];
        }

        // --- matvec: both batches, weights from registers, h broadcast LDS ---
#pragma unroll
        for (int b = 0; b < 2; b++) {
            unsigned long long a0 = 0ull, a1 = 0ull, a2 = 0ull;
            const float4* h4 = reinterpret_cast<const float4*>(sh + (cur * 2 + b) * 256 + kh * 32);
#pragma unroll
            for (int k4 = 0; k4 < 8; k4++) {
                float4 hv = h4[k4];
                unsigned long long hd;
                hd = dup2(hv.x);
                fma2(a0, w[0][k4 * 4 + 0], hd); fma2(a1, w[1][k4 * 4 + 0], hd); fma2(a2, w[2][k4 * 4 + 0], hd);
                hd = dup2(hv.y);
                fma2(a0, w[0][k4 * 4 + 1], hd); fma2(a1, w[1][k4 * 4 + 1], hd); fma2(a2, w[2][k4 * 4 + 1], hd);
                hd = dup2(hv.z);
                fma2(a0, w[0][k4 * 4 + 2], hd); fma2(a1, w[1][k4 * 4 + 2], hd); fma2(a2, w[2][k4 * 4 + 2], hd);
                hd = dup2(hv.w);
                fma2(a0, w[0][k4 * 4 + 3], hd); fma2(a1, w[1][k4 * 4 + 3], hd); fma2(a2, w[2][k4 * 4 + 3], hd);
            }
            float2* pb = pp + b * 96;   // +192 floats
            pb[0] = unpack2(a0);
            pb[1] = unpack2(a1);
            pb[2] = unpack2(a2);
        }
        __syncthreads();

        // --- reduce + gates + broadcast h_new to all 4 cluster CTAs ---
        if (t < 128) {
            float h0 = bh0, h1 = bh1, h2 = bh2;
#pragma unroll
            for (int q = 0; q < 8; q++) {
                const float* pq = pr + (q * 2 + rb) * 192;
                h0 += pq[rj];
                h1 += pq[64 + rj];
                h2 += pq[128 + rj];
            }
            float hp = sh[(cur * 2 + rb) * 256 + jg];
            float r = 1.f / (1.f + __expf(-(xr + h0)));
            float z = 1.f / (1.f + __expf(-(xz + h1)));
            float n = tanhf(xn + r * h2);
            float hn = (1.f - z) * n + z * hp;

            uint32_t la = shbase + (uint32_t)(((nxt * 2 + rb) * 256 + jg) * 4);
#pragma unroll
            for (int rr = 0; rr < 4; rr++) {
                asm volatile(
                    "{\n\t.reg .b32 ra;\n\t"
                    "mapa.shared::cluster.u32 ra, %0, %1;\n\t"
                    "st.shared::cluster.f32 [ra], %2;\n\t}"
                    :: "r"(la), "r"(rr), "f"(hn) : "memory");
            }
            long long row = (bG_r << 10) + s;
            dA[row * sA + oA + jg] = hn;
            dB[row * sB + oB + jg] = hn;
        }
        asm volatile("barrier.cluster.arrive.aligned;" ::: "memory");
        asm volatile("barrier.cluster.wait.aligned;" ::: "memory");
    }
}

// ---------------------------------------------------------------------------
extern "C" void kernel_launch(void* const* d_in, const int* in_sizes, int n_in,
                              void* d_out, int out_size) {
    const float* inp   = (const float*)d_in[0];
    const float* W_ih0 = (const float*)d_in[1];
    const float* W_hh0 = (const float*)d_in[2];
    const float* b_ih0 = (const float*)d_in[3];
    const float* b_hh0 = (const float*)d_in[4];
    const float* W_ih1 = (const float*)d_in[5];
    const float* W_hh1 = (const float*)d_in[6];
    const float* b_ih1 = (const float*)d_in[7];
    const float* b_hh1 = (const float*)d_in[8];
    float* out = (float*)d_out;

    float *xgp = nullptr, *h1p = nullptr;
    cudaGetSymbolAddress((void**)&xgp, g_xg);
    cudaGetSymbolAddress((void**)&h1p, g_h1);

    dim3 ggrid(12, 512);

    // Layer 0
    gemm_xg<<<ggrid, 256>>>(inp, W_ih0, b_ih0, xgp);
    gru_rec<<<128, 256>>>(xgp, W_hh0, b_hh0,
                          h1p, 256, 0,
                          out + BSH, 512, 0);
    // Layer 1
    gemm_xg<<<ggrid, 256>>>(h1p, W_ih1, b_ih1, xgp);
    gru_rec<<<128, 256>>>(xgp, W_hh1, b_hh1,
                          out, 256, 0,
                          out + BSH, 512, 256);
}